// round 7
// baseline (speedup 1.0000x reference)
#include <cuda_runtime.h>
#include <cstdint>
#include <cstddef>

// Problem constants
#define SEQ   512
#define BATCH 64
#define INDIM 128
#define HDIM  512

// Phase-2 decomposition: 16 clusters x 8 CTAs. Cluster owns 4 batches,
// CTA owns 64 output rows (n) of Wh, full K=512 resident in SMEM (fp32).
#define CLU    8
#define NPER   64
#define BPER   4
#define WPITCH 516     // 512 + 4 floats pad -> conflict-free LDS.128

typedef unsigned long long ull;

// ---------------------------------------------------------------------------
// Packed fp32x2 FMA (sm_103a): 2x fp32 throughput vs 3-reg FFMA.
// ---------------------------------------------------------------------------
__device__ __forceinline__ void fma2(ull& d, ull a, ull b) {
    asm("fma.rn.f32x2 %0, %1, %2, %0;" : "+l"(d) : "l"(a), "l"(b));
}
__device__ __forceinline__ float2 unpack2(ull v) {
    float2 r; asm("mov.b64 {%0, %1}, %2;" : "=f"(r.x), "=f"(r.y) : "l"(v)); return r;
}
__device__ __forceinline__ uint32_t smem_u32(const void* p) {
    return (uint32_t)__cvta_generic_to_shared(p);
}
__device__ __forceinline__ void cluster_sync_() {
    asm volatile("barrier.cluster.arrive.aligned;" ::: "memory");
    asm volatile("barrier.cluster.wait.aligned;"  ::: "memory");
}
__device__ __forceinline__ void mbar_init(uint32_t a, uint32_t cnt) {
    asm volatile("mbarrier.init.shared.b64 [%0], %1;" :: "r"(a), "r"(cnt) : "memory");
}
// Remote arrive on rank's copy of a local-smem mbarrier.
// CRITICAL: explicit .release.cluster — default is .release.cta, which does NOT
// pair with the consumer's cluster-scope acquire (this was the R5 race).
// Cumulative release: covers this warp's prior DSMEM stores (happens-before
// established by the preceding __syncwarp).
__device__ __forceinline__ void mbar_arrive_cluster(uint32_t local_mbar, uint32_t rank) {
    asm volatile(
        "{\n\t.reg .b32 ra;\n\t"
        "mapa.shared::cluster.u32 ra, %0, %1;\n\t"
        "mbarrier.arrive.release.cluster.shared::cluster.b64 _, [ra];\n\t}"
        :: "r"(local_mbar), "r"(rank) : "memory");
}
// Cluster-scope acquire folded into the try_wait: pairs with peers'
// release.cluster arrives, making their DSMEM stores visible to our LDS reads.
__device__ __forceinline__ void mbar_wait(uint32_t mbar, uint32_t parity) {
    uint32_t done;
    asm volatile(
        "{\n\t.reg .pred p;\n\t"
        "mbarrier.try_wait.parity.acquire.cluster.shared::cta.b64 p, [%1], %2;\n\t"
        "selp.b32 %0, 1, 0, p;\n\t}"
        : "=r"(done) : "r"(mbar), "r"(parity) : "memory");
    while (!done) {
        asm volatile(
            "{\n\t.reg .pred p;\n\t"
            "mbarrier.try_wait.parity.acquire.cluster.shared::cta.b64 p, [%1], %2, 0x989680;\n\t"
            "selp.b32 %0, 1, 0, p;\n\t}"
            : "=r"(done) : "r"(mbar), "r"(parity) : "memory");
    }
}
__device__ __forceinline__ void st_cluster_v4(uint32_t addr, float4 v) {
    asm volatile("st.shared::cluster.v4.f32 [%0], {%1,%2,%3,%4};"
        :: "r"(addr), "f"(v.x), "f"(v.y), "f"(v.z), "f"(v.w) : "memory");
}

// SMEM layout (bytes)
#define OFF_BARS  0                      // 2 x u64
#define OFF_XIB   16                     // float4[64]   (1024 B)
#define OFF_RED   1040                   // float[4*320] (5120 B)
#define OFF_HB    6176                   // float[2][4][512] (16384 B), 16B aligned
#define OFF_WSH   22560                  // float[64][516] (132096 B), 16B aligned
#define P2_SMEM_BYTES (OFF_WSH + NPER * WPITCH * 4)

// ===========================================================================
// Phase 1: xi = x@Wi^T + bi, written in-place into d_out's h_seq region
// (phase 2 consumes slice t then overwrites it with h_t; regenerated on every
// graph replay, so capture-safe).
// ===========================================================================
extern "C" __global__ void __launch_bounds__(256, 1)
rnn_phase1(const float* __restrict__ x, const float* __restrict__ Wi,
           const float* __restrict__ bi, float* __restrict__ out)
{
    extern __shared__ char smemraw[];
    float2* xs2 = (float2*)smemraw;                     // [128][64], duplicated pairs
    float*  ws  = (float*)(smemraw + INDIM * 64 * 8);   // [128][64]

    const int tid = threadIdx.x;
    const int m0 = blockIdx.x * 64;
    const int nb = blockIdx.y * 64;

    const int lm = tid & 63;
    const int kc = (tid >> 6) * 32;
    const float* xrow = x  + (size_t)(m0 + lm) * INDIM + kc;
    const float* wrow = Wi + (size_t)(nb + lm) * INDIM + kc;
    #pragma unroll
    for (int kk = 0; kk < 32; kk += 4) {
        float4 v = *(const float4*)(xrow + kk);
        xs2[(kc+kk+0)*64 + lm] = make_float2(v.x, v.x);
        xs2[(kc+kk+1)*64 + lm] = make_float2(v.y, v.y);
        xs2[(kc+kk+2)*64 + lm] = make_float2(v.z, v.z);
        xs2[(kc+kk+3)*64 + lm] = make_float2(v.w, v.w);
        float4 w = *(const float4*)(wrow + kk);
        ws[(kc+kk+0)*64 + lm] = w.x;
        ws[(kc+kk+1)*64 + lm] = w.y;
        ws[(kc+kk+2)*64 + lm] = w.z;
        ws[(kc+kk+3)*64 + lm] = w.w;
    }
    __syncthreads();

    const int tx = tid & 15, ty = tid >> 4;
    ull c00=0,c01=0,c10=0,c11=0,c20=0,c21=0,c30=0,c31=0;
    const ull*   xa = (const ull*)xs2 + ty * 4;
    const float* wb = ws + tx * 4;
    #pragma unroll 8
    for (int k = 0; k < INDIM; ++k) {
        ulonglong2 bb = *(const ulonglong2*)(wb + k * 64);
        ull a0 = xa[k*64 + 0]; fma2(c00, a0, bb.x); fma2(c01, a0, bb.y);
        ull a1 = xa[k*64 + 1]; fma2(c10, a1, bb.x); fma2(c11, a1, bb.y);
        ull a2 = xa[k*64 + 2]; fma2(c20, a2, bb.x); fma2(c21, a2, bb.y);
        ull a3 = xa[k*64 + 3]; fma2(c30, a3, bb.x); fma2(c31, a3, bb.y);
    }

    float4 bv = *(const float4*)(bi + nb + tx * 4);
    float* orow = out + (size_t)(m0 + ty * 4) * HDIM + nb + tx * 4;
    {
        float2 l, h;
        l = unpack2(c00); h = unpack2(c01);
        *(float4*)(orow + 0*HDIM) = make_float4(l.x+bv.x, l.y+bv.y, h.x+bv.z, h.y+bv.w);
        l = unpack2(c10); h = unpack2(c11);
        *(float4*)(orow + 1*HDIM) = make_float4(l.x+bv.x, l.y+bv.y, h.x+bv.z, h.y+bv.w);
        l = unpack2(c20); h = unpack2(c21);
        *(float4*)(orow + 2*HDIM) = make_float4(l.x+bv.x, l.y+bv.y, h.x+bv.z, h.y+bv.w);
        l = unpack2(c30); h = unpack2(c31);
        *(float4*)(orow + 3*HDIM) = make_float4(l.x+bv.x, l.y+bv.y, h.x+bv.z, h.y+bv.w);
    }
}

// ===========================================================================
// Phase 2: persistent per-cluster recurrence, mbarrier dataflow sync.
// Dot roles:      nl = tid&63 (output row), kq = tid>>6 (k quarter).
// Finalize roles: fn4 = tid&15 (n group of 4), fb = (tid>>4)&3 (batch),
//                 frp = tid>>6 (rank pair {2frp, 2frp+1}).
// h buffers hb[2][4][512] in [b][n_global] layout; producers push 16B v4
// stores directly into all peers; per-warp remote mbarrier arrives (count 64).
// Double-buffer safety: arrives for step t+1's wait are issued only after each
// warp's step-t reads (ordered by the step-t __syncthreads); writes targeting
// buffer X(t) occur at end of step t+1, strictly after every CTA's step-t dot.
// Phase parity gives distance-2 reuse. Intra-CTA redf/xibuf4 reuse is safe
// because the barrier flip requires this CTA's own warps' arrivals, which
// follow their finalize reads.
// ===========================================================================
extern "C" __global__ void __cluster_dims__(CLU, 1, 1) __launch_bounds__(256, 1)
rnn_phase2(const float* __restrict__ Wh, const float* __restrict__ bh,
           float* out, float* out_last)
{
    extern __shared__ char smemraw2[];
    float*  Wsh    = (float*)(smemraw2 + OFF_WSH);
    float*  hb     = (float*)(smemraw2 + OFF_HB);
    float*  redf   = (float*)(smemraw2 + OFF_RED);
    float4* xibuf4 = (float4*)(smemraw2 + OFF_XIB);
    const uint32_t smem_base = smem_u32(smemraw2);
    const uint32_t bar0 = smem_base + OFF_BARS;
    const uint32_t bar1 = smem_base + OFF_BARS + 8;
    const uint32_t hb_addr = smem_base + OFF_HB;

    const int tid = threadIdx.x;
    uint32_t rank; asm("mov.u32 %0, %%cluster_ctarank;" : "=r"(rank));
    const int cl  = blockIdx.x / CLU;
    const int n0  = (int)rank * NPER;
    const int gb0 = cl * BPER;

    // Init mbarriers (64 arrivals: 8 warps x 8 CTAs)
    if (tid == 0) {
        mbar_init(bar0, 64);
        mbar_init(bar1, 64);
        asm volatile("fence.mbarrier_init.release.cluster;" ::: "memory");
    }

    // Load Wh slice (coalesced), zero h buffer 0
    for (int idx = tid; idx < NPER * (HDIM / 4); idx += 256) {
        int n  = idx >> 7;
        int k4 = idx & 127;
        float4 v = *(const float4*)(Wh + (size_t)(n0 + n) * HDIM + k4 * 4);
        *(float4*)(Wsh + n * WPITCH + k4 * 4) = v;
    }
    for (int idx = tid; idx < BPER * HDIM; idx += 256) hb[idx] = 0.0f;
    __syncthreads();
    cluster_sync_();   // peers' barriers + buffers ready before any remote traffic

    // Dot role
    const int nl = tid & 63;
    const int kq = tid >> 6;
    const int k0 = kq * 128;
    // Finalize role
    const int fn4 = tid & 15;
    const int fb  = (tid >> 4) & 3;
    const int frp = tid >> 6;

    const float4 bias4 = *(const float4*)(bh + n0 + fn4 * 4);

    // Hoisted remote base addresses for this thread's two destination ranks
    uint32_t rbA, rbB;
    asm("mapa.shared::cluster.u32 %0, %1, %2;" : "=r"(rbA) : "r"(hb_addr), "r"((uint32_t)(2*frp)));
    asm("mapa.shared::cluster.u32 %0, %1, %2;" : "=r"(rbB) : "r"(hb_addr), "r"((uint32_t)(2*frp+1)));
    const uint32_t doff_base = (uint32_t)(fb * 2048 + (n0 + fn4 * 4) * 4);

    int ph0 = 0, ph1 = 0;

    for (int t = 0; t < SEQ; ++t) {
        const int X = t & 1;

        // xi prefetch BEFORE the wait: address depends only on t, so the
        // global-load latency hides under the inter-CTA mbarrier wait.
        const size_t obase = ((size_t)t * BATCH + gb0 + fb) * HDIM + n0 + fn4 * 4;
        float4 rxi;
        if (frp == 0) rxi = *(const float4*)(out + obase);

        if (t > 0) {
            if (X) { mbar_wait(bar1, ph1); ph1 ^= 1; }
            else   { mbar_wait(bar0, ph0); ph0 ^= 1; }
        }

        // ---- dot: 128-long partials for 4 batches, f32x2 ----
        ull aA0=0,aA1=0,aA2=0,aA3=0,aB0=0,aB1=0,aB2=0,aB3=0;
        const float* hp = hb + X * (BPER * HDIM) + k0;
        const ulonglong2* wr  = (const ulonglong2*)(Wsh + nl * WPITCH + k0);
        const ulonglong2* h0p = (const ulonglong2*)(hp);
        const ulonglong2* h1p = (const ulonglong2*)(hp +     HDIM);
        const ulonglong2* h2p = (const ulonglong2*)(hp + 2 * HDIM);
        const ulonglong2* h3p = (const ulonglong2*)(hp + 3 * HDIM);
        #pragma unroll 8
        for (int c = 0; c < 32; ++c) {
            ulonglong2 w  = wr[c];
            ulonglong2 v0 = h0p[c]; fma2(aA0, w.x, v0.x); fma2(aB0, w.y, v0.y);
            ulonglong2 v1 = h1p[c]; fma2(aA1, w.x, v1.x); fma2(aB1, w.y, v1.y);
            ulonglong2 v2 = h2p[c]; fma2(aA2, w.x, v2.x); fma2(aB2, w.y, v2.y);
            ulonglong2 v3 = h3p[c]; fma2(aA3, w.x, v3.x); fma2(aB3, w.y, v3.y);
        }
        {
            float2 p, q;
            float* rr = redf + kq * 320 + nl * 5;
            p = unpack2(aA0); q = unpack2(aB0); rr[0] = (p.x + q.x) + (p.y + q.y);
            p = unpack2(aA1); q = unpack2(aB1); rr[1] = (p.x + q.x) + (p.y + q.y);
            p = unpack2(aA2); q = unpack2(aB2); rr[2] = (p.x + q.x) + (p.y + q.y);
            p = unpack2(aA3); q = unpack2(aB3); rr[3] = (p.x + q.x) + (p.y + q.y);
        }
        if (frp == 0) xibuf4[fb * 16 + fn4] = rxi;
        __syncthreads();

        // ---- finalize: all 256 threads, one (fb, 4n) group each ----
        float4 xv = xibuf4[fb * 16 + fn4];
        float4 hv;
        {
            const float* rp0 = redf + (fn4 * 4) * 5 + fb;
            float r;
            r = rp0[0]  + rp0[320] + rp0[640] + rp0[960];
            hv.x = tanhf(r + bias4.x + xv.x);
            r = rp0[5]  + rp0[325] + rp0[645] + rp0[965];
            hv.y = tanhf(r + bias4.y + xv.y);
            r = rp0[10] + rp0[330] + rp0[650] + rp0[970];
            hv.z = tanhf(r + bias4.z + xv.z);
            r = rp0[15] + rp0[335] + rp0[655] + rp0[975];
            hv.w = tanhf(r + bias4.w + xv.w);
        }

        if (frp == 0) {
            *(float4*)(out + obase) = hv;
            if (t == SEQ - 1 && out_last) {
                *(float4*)(out_last + ((size_t)(gb0 + fb)) * HDIM + n0 + fn4 * 4) = hv;
            }
        }

        if (t < SEQ - 1) {
            const uint32_t doff = (uint32_t)((X ^ 1) * 8192) + doff_base;
            st_cluster_v4(rbA + doff, hv);
            st_cluster_v4(rbB + doff, hv);
            __syncwarp();
            const int lane = tid & 31;
            const uint32_t bnext = (X ? bar0 : bar1);
            if (lane < 8) mbar_arrive_cluster(bnext, (uint32_t)lane);
        }
    }
    cluster_sync_();
}

// ===========================================================================
// Launch
// ===========================================================================
extern "C" void kernel_launch(void* const* d_in, const int* in_sizes, int n_in,
                              void* d_out, int out_size) {
    (void)in_sizes; (void)n_in;
    const float* x  = (const float*)d_in[0];
    const float* Wi = (const float*)d_in[1];
    const float* bi = (const float*)d_in[2];
    const float* Wh = (const float*)d_in[3];
    const float* bh = (const float*)d_in[4];
    float* out = (float*)d_out;

    const long long SBH = (long long)SEQ * BATCH * HDIM;
    float* out_last = ((long long)out_size >= SBH + (long long)BATCH * HDIM)
                          ? out + SBH : nullptr;

    const int P1_SMEM = INDIM * 64 * 8 + INDIM * 64 * 4;   // 96 KB

    cudaFuncSetAttribute(rnn_phase1, cudaFuncAttributeMaxDynamicSharedMemorySize, P1_SMEM);
    cudaFuncSetAttribute(rnn_phase2, cudaFuncAttributeMaxDynamicSharedMemorySize, P2_SMEM_BYTES);

    rnn_phase1<<<dim3(512, 8, 1), 256, P1_SMEM>>>(x, Wi, bi, out);
    rnn_phase2<<<(BATCH / BPER) * CLU, 256, P2_SMEM_BYTES>>>(Wh, bh, out, out_last);
}

// round 10
// speedup vs baseline: 1.0567x; 1.0567x over previous
#include <cuda_runtime.h>
#include <cstdint>
#include <cstddef>

// Problem constants
#define SEQ   512
#define BATCH 64
#define INDIM 128
#define HDIM  512

#define CLU    8
#define NPER   64
#define BPER   4
#define WPITCH 516     // 512 + 4 floats pad -> conflict-free LDS.128

typedef unsigned long long ull;

__device__ __forceinline__ void fma2(ull& d, ull a, ull b) {
    asm("fma.rn.f32x2 %0, %1, %2, %0;" : "+l"(d) : "l"(a), "l"(b));
}
__device__ __forceinline__ float2 unpack2(ull v) {
    float2 r; asm("mov.b64 {%0, %1}, %2;" : "=f"(r.x), "=f"(r.y) : "l"(v)); return r;
}
__device__ __forceinline__ uint32_t smem_u32(const void* p) {
    return (uint32_t)__cvta_generic_to_shared(p);
}
__device__ __forceinline__ void cluster_sync_() {
    asm volatile("barrier.cluster.arrive.aligned;" ::: "memory");
    asm volatile("barrier.cluster.wait.aligned;"  ::: "memory");
}
__device__ __forceinline__ void mbar_init(uint32_t a, uint32_t cnt) {
    asm volatile("mbarrier.init.shared.b64 [%0], %1;" :: "r"(a), "r"(cnt) : "memory");
}
// Remote arrive: explicit .release.cluster (R5 lesson — default .release.cta
// does NOT pair with the consumer's cluster-scope acquire).
__device__ __forceinline__ void mbar_arrive_cluster(uint32_t local_mbar, uint32_t rank) {
    asm volatile(
        "{\n\t.reg .b32 ra;\n\t"
        "mapa.shared::cluster.u32 ra, %0, %1;\n\t"
        "mbarrier.arrive.release.cluster.shared::cluster.b64 _, [ra];\n\t}"
        :: "r"(local_mbar), "r"(rank) : "memory");
}
__device__ __forceinline__ void mbar_wait(uint32_t mbar, uint32_t parity) {
    uint32_t done;
    asm volatile(
        "{\n\t.reg .pred p;\n\t"
        "mbarrier.try_wait.parity.acquire.cluster.shared::cta.b64 p, [%1], %2;\n\t"
        "selp.b32 %0, 1, 0, p;\n\t}"
        : "=r"(done) : "r"(mbar), "r"(parity) : "memory");
    while (!done) {
        asm volatile(
            "{\n\t.reg .pred p;\n\t"
            "mbarrier.try_wait.parity.acquire.cluster.shared::cta.b64 p, [%1], %2, 0x989680;\n\t"
            "selp.b32 %0, 1, 0, p;\n\t}"
            : "=r"(done) : "r"(mbar), "r"(parity) : "memory");
    }
}
__device__ __forceinline__ void st_cluster_v4(uint32_t addr, float4 v) {
    asm volatile("st.shared::cluster.v4.f32 [%0], {%1,%2,%3,%4};"
        :: "r"(addr), "f"(v.x), "f"(v.y), "f"(v.z), "f"(v.w) : "memory");
}
// Fast tanh: 1 - 2/(1 + 2^(2x*log2 e)). MUFU.EX2 + MUFU.RCP, abs err ~1e-7.
__device__ __forceinline__ float fast_tanh(float x) {
    float e;
    asm("ex2.approx.f32 %0, %1;" : "=f"(e) : "f"(x * 2.8853900817779268f));
    float r;
    asm("rcp.approx.f32 %0, %1;" : "=f"(r) : "f"(e + 1.0f));
    return fmaf(-2.0f, r, 1.0f);
}

// SMEM layout (bytes)
#define OFF_BARS  0                      // 16 x u64 = 128 B   ([set=2][producer=8])
#define OFF_XIB   128                    // float4[2][64]  (2048 B)
#define OFF_RED   2176                   // float[2][1280] (10240 B)
#define OFF_HB    12416                  // float[2][4][512] (16384 B)
#define OFF_WSH   28800                  // float[64][516] (132096 B)
#define P2_SMEM_BYTES (OFF_WSH + NPER * WPITCH * 4)   // 160896

// ===========================================================================
// Phase 1: xi = x@Wi^T + bi, in-place into d_out's h_seq region.
// ===========================================================================
extern "C" __global__ void __launch_bounds__(256, 1)
rnn_phase1(const float* __restrict__ x, const float* __restrict__ Wi,
           const float* __restrict__ bi, float* __restrict__ out)
{
    extern __shared__ char smemraw[];
    float2* xs2 = (float2*)smemraw;                     // [128][64], duplicated pairs
    float*  ws  = (float*)(smemraw + INDIM * 64 * 8);   // [128][64]

    const int tid = threadIdx.x;
    const int m0 = blockIdx.x * 64;
    const int nb = blockIdx.y * 64;

    const int lm = tid & 63;
    const int kc = (tid >> 6) * 32;
    const float* xrow = x  + (size_t)(m0 + lm) * INDIM + kc;
    const float* wrow = Wi + (size_t)(nb + lm) * INDIM + kc;
    #pragma unroll
    for (int kk = 0; kk < 32; kk += 4) {
        float4 v = *(const float4*)(xrow + kk);
        xs2[(kc+kk+0)*64 + lm] = make_float2(v.x, v.x);
        xs2[(kc+kk+1)*64 + lm] = make_float2(v.y, v.y);
        xs2[(kc+kk+2)*64 + lm] = make_float2(v.z, v.z);
        xs2[(kc+kk+3)*64 + lm] = make_float2(v.w, v.w);
        float4 w = *(const float4*)(wrow + kk);
        ws[(kc+kk+0)*64 + lm] = w.x;
        ws[(kc+kk+1)*64 + lm] = w.y;
        ws[(kc+kk+2)*64 + lm] = w.z;
        ws[(kc+kk+3)*64 + lm] = w.w;
    }
    __syncthreads();

    const int tx = tid & 15, ty = tid >> 4;
    ull c00=0,c01=0,c10=0,c11=0,c20=0,c21=0,c30=0,c31=0;
    const ull*   xa = (const ull*)xs2 + ty * 4;
    const float* wb = ws + tx * 4;
    #pragma unroll 8
    for (int k = 0; k < INDIM; ++k) {
        ulonglong2 bb = *(const ulonglong2*)(wb + k * 64);
        ull a0 = xa[k*64 + 0]; fma2(c00, a0, bb.x); fma2(c01, a0, bb.y);
        ull a1 = xa[k*64 + 1]; fma2(c10, a1, bb.x); fma2(c11, a1, bb.y);
        ull a2 = xa[k*64 + 2]; fma2(c20, a2, bb.x); fma2(c21, a2, bb.y);
        ull a3 = xa[k*64 + 3]; fma2(c30, a3, bb.x); fma2(c31, a3, bb.y);
    }

    float4 bv = *(const float4*)(bi + nb + tx * 4);
    float* orow = out + (size_t)(m0 + ty * 4) * HDIM + nb + tx * 4;
    {
        float2 l, h;
        l = unpack2(c00); h = unpack2(c01);
        *(float4*)(orow + 0*HDIM) = make_float4(l.x+bv.x, l.y+bv.y, h.x+bv.z, h.y+bv.w);
        l = unpack2(c10); h = unpack2(c11);
        *(float4*)(orow + 1*HDIM) = make_float4(l.x+bv.x, l.y+bv.y, h.x+bv.z, h.y+bv.w);
        l = unpack2(c20); h = unpack2(c21);
        *(float4*)(orow + 2*HDIM) = make_float4(l.x+bv.x, l.y+bv.y, h.x+bv.z, h.y+bv.w);
        l = unpack2(c30); h = unpack2(c31);
        *(float4*)(orow + 3*HDIM) = make_float4(l.x+bv.x, l.y+bv.y, h.x+bv.z, h.y+bv.w);
    }
}

// ===========================================================================
// Phase 2: persistent per-cluster recurrence with FINE-GRAINED dataflow.
// bars[set][r] (count 2): producer rank r's warp-pair frp pushes r's slice to
// dests {2frp, 2frp+1} and arrives on each dest's bars[set][r]. Consumer warp
// kq waits only bars[X][2kq], bars[X][2kq+1] — exactly the producers of its
// k-slice. Writing warps == the warps that waited on the dest's prior-step
// arrive, so distance-2 parity buffer reuse is provably race-free.
// redf/xibuf are parity double-buffered to allow intra-CTA warp drift.
// ===========================================================================
extern "C" __global__ void __cluster_dims__(CLU, 1, 1) __launch_bounds__(256, 1)
rnn_phase2(const float* __restrict__ Wh, const float* __restrict__ bh,
           float* out, float* out_last)
{
    extern __shared__ char smemraw2[];
    float*  Wsh    = (float*)(smemraw2 + OFF_WSH);
    float*  hb     = (float*)(smemraw2 + OFF_HB);
    float*  redf   = (float*)(smemraw2 + OFF_RED);     // [2][1280]
    float4* xibuf4 = (float4*)(smemraw2 + OFF_XIB);    // [2][64]
    const uint32_t smem_base = smem_u32(smemraw2);
    const uint32_t hb_addr = smem_base + OFF_HB;

    const int tid = threadIdx.x;
    uint32_t rank; asm("mov.u32 %0, %%cluster_ctarank;" : "=r"(rank));
    const int cl  = blockIdx.x / CLU;
    const int n0  = (int)rank * NPER;
    const int gb0 = cl * BPER;

    // Init 16 mbarriers, count 2 each (producer's two pushing warps)
    if (tid == 0) {
        #pragma unroll
        for (int i = 0; i < 16; ++i) mbar_init(smem_base + OFF_BARS + i * 8, 2);
        asm volatile("fence.mbarrier_init.release.cluster;" ::: "memory");
    }

    // Load Wh slice (coalesced), zero h buffer 0
    for (int idx = tid; idx < NPER * (HDIM / 4); idx += 256) {
        int n  = idx >> 7;
        int k4 = idx & 127;
        float4 v = *(const float4*)(Wh + (size_t)(n0 + n) * HDIM + k4 * 4);
        *(float4*)(Wsh + n * WPITCH + k4 * 4) = v;
    }
    for (int idx = tid; idx < BPER * HDIM; idx += 256) hb[idx] = 0.0f;
    __syncthreads();
    cluster_sync_();   // peers' barriers + buffers ready before any remote traffic

    // Dot role
    const int nl = tid & 63;
    const int kq = tid >> 6;           // warp-pair id == k-quarter
    const int k0 = kq * 128;
    // Finalize role
    const int fn4 = tid & 15;
    const int fb  = (tid >> 4) & 3;
    const int frp = tid >> 6;          // == kq
    const int lane = tid & 31;

    const float4 bias4 = *(const float4*)(bh + n0 + fn4 * 4);

    // Remote h-buffer bases for this thread's two destination ranks
    uint32_t rbA, rbB;
    asm("mapa.shared::cluster.u32 %0, %1, %2;" : "=r"(rbA) : "r"(hb_addr), "r"((uint32_t)(2*frp)));
    asm("mapa.shared::cluster.u32 %0, %1, %2;" : "=r"(rbB) : "r"(hb_addr), "r"((uint32_t)(2*frp+1)));
    const uint32_t doff_base = (uint32_t)(fb * 2048 + (n0 + fn4 * 4) * 4);

    // My two wait-barrier offsets within a set (producers of my k-slice)
    const uint32_t barW0 = smem_base + OFF_BARS + (uint32_t)(2*kq)     * 8;
    const uint32_t barW1 = smem_base + OFF_BARS + (uint32_t)(2*kq + 1) * 8;
    // Arrive target: dest's bars[set][my rank]; set stride = 64 B
    const uint32_t barMy = smem_base + OFF_BARS + rank * 8;

    int ph0 = 0, ph1 = 0;

    for (int t = 0; t < SEQ; ++t) {
        const int X = t & 1;

        // xi prefetch before the wait (latency hides under inter-CTA skew)
        const size_t obase = ((size_t)t * BATCH + gb0 + fb) * HDIM + n0 + fn4 * 4;
        float4 rxi;
        if (frp == 0) rxi = *(const float4*)(out + obase);

        if (t > 0) {
            const uint32_t so = (uint32_t)X * 64u;
            const int ph = X ? ph1 : ph0;
            mbar_wait(barW0 + so, ph);
            mbar_wait(barW1 + so, ph);
            if (X) ph1 ^= 1; else ph0 ^= 1;
        }

        // ---- dot: 128-long partials for 4 batches, f32x2 ----
        ull aA0=0,aA1=0,aA2=0,aA3=0,aB0=0,aB1=0,aB2=0,aB3=0;
        const float* hp = hb + X * (BPER * HDIM) + k0;
        const ulonglong2* wr  = (const ulonglong2*)(Wsh + nl * WPITCH + k0);
        const ulonglong2* h0p = (const ulonglong2*)(hp);
        const ulonglong2* h1p = (const ulonglong2*)(hp +     HDIM);
        const ulonglong2* h2p = (const ulonglong2*)(hp + 2 * HDIM);
        const ulonglong2* h3p = (const ulonglong2*)(hp + 3 * HDIM);
        #pragma unroll 8
        for (int c = 0; c < 32; ++c) {
            ulonglong2 w  = wr[c];
            ulonglong2 v0 = h0p[c]; fma2(aA0, w.x, v0.x); fma2(aB0, w.y, v0.y);
            ulonglong2 v1 = h1p[c]; fma2(aA1, w.x, v1.x); fma2(aB1, w.y, v1.y);
            ulonglong2 v2 = h2p[c]; fma2(aA2, w.x, v2.x); fma2(aB2, w.y, v2.y);
            ulonglong2 v3 = h3p[c]; fma2(aA3, w.x, v3.x); fma2(aB3, w.y, v3.y);
        }
        {
            float2 p, q;
            float* rr = redf + X * 1280 + kq * 320 + nl * 5;
            p = unpack2(aA0); q = unpack2(aB0); rr[0] = (p.x + q.x) + (p.y + q.y);
            p = unpack2(aA1); q = unpack2(aB1); rr[1] = (p.x + q.x) + (p.y + q.y);
            p = unpack2(aA2); q = unpack2(aB2); rr[2] = (p.x + q.x) + (p.y + q.y);
            p = unpack2(aA3); q = unpack2(aB3); rr[3] = (p.x + q.x) + (p.y + q.y);
        }
        if (frp == 0) xibuf4[X * 64 + fb * 16 + fn4] = rxi;
        __syncthreads();

        // ---- finalize: all 256 threads, one (fb, 4n) group each ----
        float4 xv = xibuf4[X * 64 + fb * 16 + fn4];
        float4 hv;
        {
            const float* rp0 = redf + X * 1280 + (fn4 * 4) * 5 + fb;
            float r;
            r = rp0[0]  + rp0[320] + rp0[640] + rp0[960];
            hv.x = fast_tanh(r + bias4.x + xv.x);
            r = rp0[5]  + rp0[325] + rp0[645] + rp0[965];
            hv.y = fast_tanh(r + bias4.y + xv.y);
            r = rp0[10] + rp0[330] + rp0[650] + rp0[970];
            hv.z = fast_tanh(r + bias4.z + xv.z);
            r = rp0[15] + rp0[335] + rp0[655] + rp0[975];
            hv.w = fast_tanh(r + bias4.w + xv.w);
        }

        // Push FIRST (critical path), then arrive, then global stores.
        if (t < SEQ - 1) {
            const uint32_t doff = (uint32_t)((X ^ 1) * 8192) + doff_base;
            st_cluster_v4(rbA + doff, hv);
            st_cluster_v4(rbB + doff, hv);
            __syncwarp();
            if (lane < 2) {
                // dest (2*frp+lane)'s bars[X^1][my rank]
                mbar_arrive_cluster(barMy + (uint32_t)(X ^ 1) * 64u,
                                    (uint32_t)(2 * frp + lane));
            }
        }

        if (frp == 0) {
            *(float4*)(out + obase) = hv;
            if (t == SEQ - 1 && out_last) {
                *(float4*)(out_last + ((size_t)(gb0 + fb)) * HDIM + n0 + fn4 * 4) = hv;
            }
        }
    }
    cluster_sync_();
}

// ===========================================================================
// Launch
// ===========================================================================
extern "C" void kernel_launch(void* const* d_in, const int* in_sizes, int n_in,
                              void* d_out, int out_size) {
    (void)in_sizes; (void)n_in;
    const float* x  = (const float*)d_in[0];
    const float* Wi = (const float*)d_in[1];
    const float* bi = (const float*)d_in[2];
    const float* Wh = (const float*)d_in[3];
    const float* bh = (const float*)d_in[4];
    float* out = (float*)d_out;

    const long long SBH = (long long)SEQ * BATCH * HDIM;
    float* out_last = ((long long)out_size >= SBH + (long long)BATCH * HDIM)
                          ? out + SBH : nullptr;

    const int P1_SMEM = INDIM * 64 * 8 + INDIM * 64 * 4;   // 96 KB

    cudaFuncSetAttribute(rnn_phase1, cudaFuncAttributeMaxDynamicSharedMemorySize, P1_SMEM);
    cudaFuncSetAttribute(rnn_phase2, cudaFuncAttributeMaxDynamicSharedMemorySize, P2_SMEM_BYTES);

    rnn_phase1<<<dim3(512, 8, 1), 256, P1_SMEM>>>(x, Wi, bi, out);
    rnn_phase2<<<(BATCH / BPER) * CLU, 256, P2_SMEM_BYTES>>>(Wh, bh, out, out_last);
}

// round 13
// speedup vs baseline: 1.3017x; 1.2319x over previous
#include <cuda_runtime.h>
#include <cstdint>
#include <cstddef>

// Problem constants
#define SEQ   512
#define BATCH 64
#define INDIM 128
#define HDIM  512

#define CLU    8
#define NPER   64
#define BPER   4
#define WPITCH 516     // 512 + 4 floats pad -> conflict-free LDS.128

typedef unsigned long long ull;

__device__ __forceinline__ void fma2(ull& d, ull a, ull b) {
    asm("fma.rn.f32x2 %0, %1, %2, %0;" : "+l"(d) : "l"(a), "l"(b));
}
__device__ __forceinline__ float2 unpack2(ull v) {
    float2 r; asm("mov.b64 {%0, %1}, %2;" : "=f"(r.x), "=f"(r.y) : "l"(v)); return r;
}
__device__ __forceinline__ uint32_t smem_u32(const void* p) {
    return (uint32_t)__cvta_generic_to_shared(p);
}
__device__ __forceinline__ void cluster_sync_() {
    asm volatile("barrier.cluster.arrive.aligned;" ::: "memory");
    asm volatile("barrier.cluster.wait.aligned;"  ::: "memory");
}
__device__ __forceinline__ void mbar_init(uint32_t a, uint32_t cnt) {
    asm volatile("mbarrier.init.shared.b64 [%0], %1;" :: "r"(a), "r"(cnt) : "memory");
}
// Remote arrive: explicit .release.cluster (R5 lesson — default .release.cta
// does NOT pair with the consumer's cluster-scope acquire).
__device__ __forceinline__ void mbar_arrive_cluster(uint32_t local_mbar, uint32_t rank) {
    asm volatile(
        "{\n\t.reg .b32 ra;\n\t"
        "mapa.shared::cluster.u32 ra, %0, %1;\n\t"
        "mbarrier.arrive.release.cluster.shared::cluster.b64 _, [ra];\n\t}"
        :: "r"(local_mbar), "r"(rank) : "memory");
}
__device__ __forceinline__ void mbar_wait(uint32_t mbar, uint32_t parity) {
    uint32_t done;
    asm volatile(
        "{\n\t.reg .pred p;\n\t"
        "mbarrier.try_wait.parity.acquire.cluster.shared::cta.b64 p, [%1], %2;\n\t"
        "selp.b32 %0, 1, 0, p;\n\t}"
        : "=r"(done) : "r"(mbar), "r"(parity) : "memory");
    while (!done) {
        asm volatile(
            "{\n\t.reg .pred p;\n\t"
            "mbarrier.try_wait.parity.acquire.cluster.shared::cta.b64 p, [%1], %2, 0x989680;\n\t"
            "selp.b32 %0, 1, 0, p;\n\t}"
            : "=r"(done) : "r"(mbar), "r"(parity) : "memory");
    }
}
__device__ __forceinline__ void st_cluster_v4(uint32_t addr, float4 v) {
    asm volatile("st.shared::cluster.v4.f32 [%0], {%1,%2,%3,%4};"
        :: "r"(addr), "f"(v.x), "f"(v.y), "f"(v.z), "f"(v.w) : "memory");
}
// Fast tanh: 1 - 2/(1 + 2^(2x*log2 e)). MUFU.EX2 + MUFU.RCP, abs err ~1e-7.
__device__ __forceinline__ float fast_tanh(float x) {
    float e;
    asm("ex2.approx.f32 %0, %1;" : "=f"(e) : "f"(x * 2.8853900817779268f));
    float r;
    asm("rcp.approx.f32 %0, %1;" : "=f"(r) : "f"(e + 1.0f));
    return fmaf(-2.0f, r, 1.0f);
}

// SMEM layout (bytes)
#define OFF_BARS  0                      // 16 x u64 = 128 B   ([set=2][producer=8])
#define OFF_XIB   128                    // float4[2][64]  (2048 B)
#define OFF_RED   2176                   // float[2][1280] (10240 B)
#define OFF_HB    12416                  // float[2][4][512] (16384 B)
#define OFF_WSH   28800                  // float[64][516] (132096 B) — staging only
#define P2_SMEM_BYTES (OFF_WSH + NPER * WPITCH * 4)   // 160896

// ===========================================================================
// Phase 1: xi = x@Wi^T + bi, in-place into d_out's h_seq region.
// ===========================================================================
extern "C" __global__ void __launch_bounds__(256, 1)
rnn_phase1(const float* __restrict__ x, const float* __restrict__ Wi,
           const float* __restrict__ bi, float* __restrict__ out)
{
    extern __shared__ char smemraw[];
    float2* xs2 = (float2*)smemraw;                     // [128][64], duplicated pairs
    float*  ws  = (float*)(smemraw + INDIM * 64 * 8);   // [128][64]

    const int tid = threadIdx.x;
    const int m0 = blockIdx.x * 64;
    const int nb = blockIdx.y * 64;

    const int lm = tid & 63;
    const int kc = (tid >> 6) * 32;
    const float* xrow = x  + (size_t)(m0 + lm) * INDIM + kc;
    const float* wrow = Wi + (size_t)(nb + lm) * INDIM + kc;
    #pragma unroll
    for (int kk = 0; kk < 32; kk += 4) {
        float4 v = *(const float4*)(xrow + kk);
        xs2[(kc+kk+0)*64 + lm] = make_float2(v.x, v.x);
        xs2[(kc+kk+1)*64 + lm] = make_float2(v.y, v.y);
        xs2[(kc+kk+2)*64 + lm] = make_float2(v.z, v.z);
        xs2[(kc+kk+3)*64 + lm] = make_float2(v.w, v.w);
        float4 w = *(const float4*)(wrow + kk);
        ws[(kc+kk+0)*64 + lm] = w.x;
        ws[(kc+kk+1)*64 + lm] = w.y;
        ws[(kc+kk+2)*64 + lm] = w.z;
        ws[(kc+kk+3)*64 + lm] = w.w;
    }
    __syncthreads();

    const int tx = tid & 15, ty = tid >> 4;
    ull c00=0,c01=0,c10=0,c11=0,c20=0,c21=0,c30=0,c31=0;
    const ull*   xa = (const ull*)xs2 + ty * 4;
    const float* wb = ws + tx * 4;
    #pragma unroll 8
    for (int k = 0; k < INDIM; ++k) {
        ulonglong2 bb = *(const ulonglong2*)(wb + k * 64);
        ull a0 = xa[k*64 + 0]; fma2(c00, a0, bb.x); fma2(c01, a0, bb.y);
        ull a1 = xa[k*64 + 1]; fma2(c10, a1, bb.x); fma2(c11, a1, bb.y);
        ull a2 = xa[k*64 + 2]; fma2(c20, a2, bb.x); fma2(c21, a2, bb.y);
        ull a3 = xa[k*64 + 3]; fma2(c30, a3, bb.x); fma2(c31, a3, bb.y);
    }

    float4 bv = *(const float4*)(bi + nb + tx * 4);
    float* orow = out + (size_t)(m0 + ty * 4) * HDIM + nb + tx * 4;
    {
        float2 l, h;
        l = unpack2(c00); h = unpack2(c01);
        *(float4*)(orow + 0*HDIM) = make_float4(l.x+bv.x, l.y+bv.y, h.x+bv.z, h.y+bv.w);
        l = unpack2(c10); h = unpack2(c11);
        *(float4*)(orow + 1*HDIM) = make_float4(l.x+bv.x, l.y+bv.y, h.x+bv.z, h.y+bv.w);
        l = unpack2(c20); h = unpack2(c21);
        *(float4*)(orow + 2*HDIM) = make_float4(l.x+bv.x, l.y+bv.y, h.x+bv.z, h.y+bv.w);
        l = unpack2(c30); h = unpack2(c31);
        *(float4*)(orow + 3*HDIM) = make_float4(l.x+bv.x, l.y+bv.y, h.x+bv.z, h.y+bv.w);
    }
}

// ===========================================================================
// Phase 2: persistent per-cluster recurrence, fine-grained dataflow,
// Wh held ENTIRELY IN REGISTERS (64 f32x2 pairs = 128 regs/thread; 32K regs
// per CTA = half the RF). The dot reads only broadcast h from SMEM — the
// 1024 Wh crossbar wavefronts per step are gone.
// Protocol identical to the passing R10 kernel.
// ===========================================================================
extern "C" __global__ void __cluster_dims__(CLU, 1, 1) __launch_bounds__(256, 1)
rnn_phase2(const float* __restrict__ Wh, const float* __restrict__ bh,
           float* out, float* out_last)
{
    extern __shared__ char smemraw2[];
    float*  Wsh    = (float*)(smemraw2 + OFF_WSH);     // staging only
    float*  hb     = (float*)(smemraw2 + OFF_HB);
    float*  redf   = (float*)(smemraw2 + OFF_RED);     // [2][1280]
    float4* xibuf4 = (float4*)(smemraw2 + OFF_XIB);    // [2][64]
    const uint32_t smem_base = smem_u32(smemraw2);
    const uint32_t hb_addr = smem_base + OFF_HB;

    const int tid = threadIdx.x;
    uint32_t rank; asm("mov.u32 %0, %%cluster_ctarank;" : "=r"(rank));
    const int cl  = blockIdx.x / CLU;
    const int n0  = (int)rank * NPER;
    const int gb0 = cl * BPER;

    // Init 16 mbarriers, count 2 each (producer's two pushing warps)
    if (tid == 0) {
        #pragma unroll
        for (int i = 0; i < 16; ++i) mbar_init(smem_base + OFF_BARS + i * 8, 2);
        asm volatile("fence.mbarrier_init.release.cluster;" ::: "memory");
    }

    // Stage Wh slice into SMEM (coalesced), zero h buffer 0
    for (int idx = tid; idx < NPER * (HDIM / 4); idx += 256) {
        int n  = idx >> 7;
        int k4 = idx & 127;
        float4 v = *(const float4*)(Wh + (size_t)(n0 + n) * HDIM + k4 * 4);
        *(float4*)(Wsh + n * WPITCH + k4 * 4) = v;
    }
    for (int idx = tid; idx < BPER * HDIM; idx += 256) hb[idx] = 0.0f;
    __syncthreads();

    // Dot role
    const int nl = tid & 63;
    const int kq = tid >> 6;           // warp-pair id == k-quarter
    const int k0 = kq * 128;
    // Finalize role
    const int fn4 = tid & 15;
    const int fb  = (tid >> 4) & 3;
    const int frp = tid >> 6;          // == kq
    const int lane = tid & 31;

    // ---- Pull my Wh row-segment into registers: 64 f32x2 pairs ----
    ull w[64];
    {
        const ulonglong2* wr0 = (const ulonglong2*)(Wsh + nl * WPITCH + k0);
        #pragma unroll
        for (int c = 0; c < 32; ++c) {
            ulonglong2 tw = wr0[c];
            w[2*c]   = tw.x;
            w[2*c+1] = tw.y;
        }
    }

    cluster_sync_();   // peers' barriers + buffers ready before any remote traffic

    const float4 bias4 = *(const float4*)(bh + n0 + fn4 * 4);

    // Remote h-buffer bases for this thread's two destination ranks
    uint32_t rbA, rbB;
    asm("mapa.shared::cluster.u32 %0, %1, %2;" : "=r"(rbA) : "r"(hb_addr), "r"((uint32_t)(2*frp)));
    asm("mapa.shared::cluster.u32 %0, %1, %2;" : "=r"(rbB) : "r"(hb_addr), "r"((uint32_t)(2*frp+1)));
    const uint32_t doff_base = (uint32_t)(fb * 2048 + (n0 + fn4 * 4) * 4);

    // My two wait-barrier offsets within a set (producers of my k-slice)
    const uint32_t barW0 = smem_base + OFF_BARS + (uint32_t)(2*kq)     * 8;
    const uint32_t barW1 = smem_base + OFF_BARS + (uint32_t)(2*kq + 1) * 8;
    // Arrive target: dest's bars[set][my rank]; set stride = 64 B
    const uint32_t barMy = smem_base + OFF_BARS + rank * 8;

    int ph0 = 0, ph1 = 0;

    for (int t = 0; t < SEQ; ++t) {
        const int X = t & 1;

        // xi prefetch before the wait (latency hides under inter-CTA skew)
        const size_t obase = ((size_t)t * BATCH + gb0 + fb) * HDIM + n0 + fn4 * 4;
        float4 rxi;
        if (frp == 0) rxi = *(const float4*)(out + obase);

        if (t > 0) {
            const uint32_t so = (uint32_t)X * 64u;
            const int ph = X ? ph1 : ph0;
            mbar_wait(barW0 + so, ph);
            mbar_wait(barW1 + so, ph);
            if (X) ph1 ^= 1; else ph0 ^= 1;
        }

        // ---- dot: 128-long partials for 4 batches; Wh from REGISTERS,
        //      h via broadcast LDS.128 only ----
        ull aA0=0,aA1=0,aA2=0,aA3=0,aB0=0,aB1=0,aB2=0,aB3=0;
        const float* hp = hb + X * (BPER * HDIM) + k0;
        const ulonglong2* h0p = (const ulonglong2*)(hp);
        const ulonglong2* h1p = (const ulonglong2*)(hp +     HDIM);
        const ulonglong2* h2p = (const ulonglong2*)(hp + 2 * HDIM);
        const ulonglong2* h3p = (const ulonglong2*)(hp + 3 * HDIM);
        #pragma unroll
        for (int c = 0; c < 32; ++c) {
            const ull wx = w[2*c], wy = w[2*c+1];
            ulonglong2 v0 = h0p[c]; fma2(aA0, wx, v0.x); fma2(aB0, wy, v0.y);
            ulonglong2 v1 = h1p[c]; fma2(aA1, wx, v1.x); fma2(aB1, wy, v1.y);
            ulonglong2 v2 = h2p[c]; fma2(aA2, wx, v2.x); fma2(aB2, wy, v2.y);
            ulonglong2 v3 = h3p[c]; fma2(aA3, wx, v3.x); fma2(aB3, wy, v3.y);
        }
        {
            float2 p, q;
            float* rr = redf + X * 1280 + kq * 320 + nl * 5;
            p = unpack2(aA0); q = unpack2(aB0); rr[0] = (p.x + q.x) + (p.y + q.y);
            p = unpack2(aA1); q = unpack2(aB1); rr[1] = (p.x + q.x) + (p.y + q.y);
            p = unpack2(aA2); q = unpack2(aB2); rr[2] = (p.x + q.x) + (p.y + q.y);
            p = unpack2(aA3); q = unpack2(aB3); rr[3] = (p.x + q.x) + (p.y + q.y);
        }
        if (frp == 0) xibuf4[X * 64 + fb * 16 + fn4] = rxi;
        __syncthreads();

        // ---- finalize: all 256 threads, one (fb, 4n) group each ----
        float4 xv = xibuf4[X * 64 + fb * 16 + fn4];
        float4 hv;
        {
            const float* rp0 = redf + X * 1280 + (fn4 * 4) * 5 + fb;
            float r;
            r = rp0[0]  + rp0[320] + rp0[640] + rp0[960];
            hv.x = fast_tanh(r + bias4.x + xv.x);
            r = rp0[5]  + rp0[325] + rp0[645] + rp0[965];
            hv.y = fast_tanh(r + bias4.y + xv.y);
            r = rp0[10] + rp0[330] + rp0[650] + rp0[970];
            hv.z = fast_tanh(r + bias4.z + xv.z);
            r = rp0[15] + rp0[335] + rp0[655] + rp0[975];
            hv.w = fast_tanh(r + bias4.w + xv.w);
        }

        // Push FIRST (critical path), then arrive, then global stores.
        if (t < SEQ - 1) {
            const uint32_t doff = (uint32_t)((X ^ 1) * 8192) + doff_base;
            st_cluster_v4(rbA + doff, hv);
            st_cluster_v4(rbB + doff, hv);
            __syncwarp();
            if (lane < 2) {
                // dest (2*frp+lane)'s bars[X^1][my rank]
                mbar_arrive_cluster(barMy + (uint32_t)(X ^ 1) * 64u,
                                    (uint32_t)(2 * frp + lane));
            }
        }

        if (frp == 0) {
            *(float4*)(out + obase) = hv;
            if (t == SEQ - 1 && out_last) {
                *(float4*)(out_last + ((size_t)(gb0 + fb)) * HDIM + n0 + fn4 * 4) = hv;
            }
        }
    }
    cluster_sync_();
}

// ===========================================================================
// Launch
// ===========================================================================
extern "C" void kernel_launch(void* const* d_in, const int* in_sizes, int n_in,
                              void* d_out, int out_size) {
    (void)in_sizes; (void)n_in;
    const float* x  = (const float*)d_in[0];
    const float* Wi = (const float*)d_in[1];
    const float* bi = (const float*)d_in[2];
    const float* Wh = (const float*)d_in[3];
    const float* bh = (const float*)d_in[4];
    float* out = (float*)d_out;

    const long long SBH = (long long)SEQ * BATCH * HDIM;
    float* out_last = ((long long)out_size >= SBH + (long long)BATCH * HDIM)
                          ? out + SBH : nullptr;

    const int P1_SMEM = INDIM * 64 * 8 + INDIM * 64 * 4;   // 96 KB

    cudaFuncSetAttribute(rnn_phase1, cudaFuncAttributeMaxDynamicSharedMemorySize, P1_SMEM);
    cudaFuncSetAttribute(rnn_phase2, cudaFuncAttributeMaxDynamicSharedMemorySize, P2_SMEM_BYTES);

    rnn_phase1<<<dim3(512, 8, 1), 256, P1_SMEM>>>(x, Wi, bi, out);
    rnn_phase2<<<(BATCH / BPER) * CLU, 256, P2_SMEM_BYTES>>>(Wh, bh, out, out_last);
}